// round 8
// baseline (speedup 1.0000x reference)
#include <cuda_runtime.h>
#include <math.h>
#include <stdint.h>

#define NUM_CLASS 20
#define IGNORE 255
#define DD 256
#define HH 256
#define WW 32
#define SPATIAL (DD*HH*WW)     // 2,097,152
#define TV 512                 // voxels per block tile
#define NBLOCKS (SPATIAL/TV)   // 4096
#define CHUNKS (NUM_CLASS*TV*4/16)   // 2560 16-byte chunks per tile

__device__ double g_num;        // zero at module load; reset by last block each run
__device__ double g_den;
__device__ unsigned g_bcount;

__device__ __forceinline__ float gval(int a, int b) {
    // sum_c |onehot(a)-onehot(b)|, onehot(IGNORE)=0
    if (a == b) return 0.0f;
    if (a == IGNORE || b == IGNORE) return 1.0f;
    return 2.0f;
}

__global__ void __launch_bounds__(256)
loss_kernel(const float* __restrict__ pred,
            const int*   __restrict__ tgt,
            const float* __restrict__ cw,
            float* __restrict__ out) {
    __shared__ float s_pred[NUM_CLASS * TV];   // 40 KB
    __shared__ float s_num[8], s_den[8];

    const int tile = blockIdx.x * TV;
    const int tid = threadIdx.x;

    // ---- stage 20 channels x 512 voxels into SMEM via cp.async (.cg: L2 only) ----
    #pragma unroll
    for (int k = tid; k < CHUNKS; k += 256) {
        const int c   = k >> 7;          // chunk / 128
        const int off = (k & 127) << 2;  // float offset within channel row
        const float* src = pred + c * SPATIAL + tile + off;
        uint32_t dst = (uint32_t)__cvta_generic_to_shared(&s_pred[c * TV + off]);
        asm volatile("cp.async.cg.shared.global [%0], [%1], 16;\n" :: "r"(dst), "l"(src));
    }
    asm volatile("cp.async.commit_group;\n");
    asm volatile("cp.async.wait_group 0;\n");
    __syncthreads();

    // ---- compute: 2 voxels per thread (vox = tid, tid+256) ----
    float num = 0.0f, den = 0.0f;

    #pragma unroll
    for (int half = 0; half < 2; half++) {
        const int vox = tid + half * 256;
        const int s = tile + vox;

        const int t = __ldg(&tgt[s]);
        const bool valid = (t != IGNORE);
        const int tc = valid ? t : 0;

        // softmax denominator from SMEM (no max-subtraction: inputs ~N(0,1))
        float sum = 0.0f;
        #pragma unroll
        for (int c = 0; c < NUM_CLASS; c++) {
            sum += __expf(s_pred[c * TV + vox]);   // MUFU.EX2, conflict-free LDS
        }
        const float vt = s_pred[tc * TV + vox];    // dynamic smem index, conflict-free
        const float logp_t = vt - __logf(sum);

        const float w = __ldg(&cw[tc]);
        const float loss = valid ? (-w * logp_t) : 0.0f;
        den += valid ? w : 0.0f;

        // ---- LGA weight ----
        const int wq = s & (WW - 1);               // == lane id (warp spans one W row)
        const int h  = (s >> 5) & (HH - 1);
        const int d  = s >> 13;
        const int sd = WW * HH;

        float lga;
        {   // W axis: adjacent lanes hold neighbors; shfl self-clamps at warp edges -> t
            int a = __shfl_up_sync(0xFFFFFFFFu, t, 1);
            int b = __shfl_down_sync(0xFFFFFFFFu, t, 1);
            float sc = (wq == 0 || wq == WW - 1) ? 1.0f : 0.5f;
            lga = sc * gval(a, b);
        }
        {   // H axis
            const int thm = (h == 0)      ? t : __ldg(&tgt[s - WW]);
            const int thp = (h == HH - 1) ? t : __ldg(&tgt[s + WW]);
            float sc = (h == 0 || h == HH - 1) ? 1.0f : 0.5f;
            lga += sc * gval(thm, thp);
        }
        {   // D axis
            const int tdm = (d == 0)      ? t : __ldg(&tgt[s - sd]);
            const int tdp = (d == DD - 1) ? t : __ldg(&tgt[s + sd]);
            float sc = (d == 0 || d == DD - 1) ? 1.0f : 0.5f;
            lga += sc * gval(tdm, tdp);
        }

        num += loss * (1.0f + lga);   // ALPHA=1, BETA=1
    }

    // ---- reduction: warp shuffle -> shared -> global double atomics ----
    #pragma unroll
    for (int off = 16; off > 0; off >>= 1) {
        num += __shfl_down_sync(0xFFFFFFFFu, num, off);
        den += __shfl_down_sync(0xFFFFFFFFu, den, off);
    }
    const int lane = tid & 31;
    const int wid  = tid >> 5;
    if (lane == 0) { s_num[wid] = num; s_den[wid] = den; }
    __syncthreads();

    if (tid == 0) {
        float bn = 0.f, bd = 0.f;
        #pragma unroll
        for (int i = 0; i < 8; i++) { bn += s_num[i]; bd += s_den[i]; }
        atomicAdd(&g_num, (double)bn);
        atomicAdd(&g_den, (double)bd);
        __threadfence();
        unsigned done = atomicAdd(&g_bcount, 1u);
        if (done == (unsigned)(gridDim.x - 1)) {
            double n  = atomicAdd(&g_num, 0.0);
            double dd = atomicAdd(&g_den, 0.0);
            out[0] = (float)(n / dd);
            g_num = 0.0; g_den = 0.0; g_bcount = 0u;
        }
    }
}

extern "C" void kernel_launch(void* const* d_in, const int* in_sizes, int n_in,
                              void* d_out, int out_size) {
    const float* pred = (const float*)d_in[0];
    const int*   tgt  = (const int*)d_in[1];
    const float* cw   = (const float*)d_in[2];
    float* out = (float*)d_out;

    loss_kernel<<<NBLOCKS, 256>>>(pred, tgt, cw, out);
}

// round 9
// speedup vs baseline: 1.0832x; 1.0832x over previous
#include <cuda_runtime.h>
#include <math.h>
#include <stdint.h>

#define NUM_CLASS 20
#define IGNORE 255
#define DD 256
#define HH 256
#define WW 32
#define SPATIAL (DD*HH*WW)     // 2,097,152
#define TV 256                 // voxels per tile (= one block-wide pass)
#define NTILES (SPATIAL/TV)    // 8192
#define GRID 740               // 148 SMs x 5 persistent CTAs
#define CHUNKS (NUM_CLASS*TV*4/16)   // 1280 16-byte chunks per tile (5 per thread)

__device__ double g_num;        // zero at module load; reset by last block each run
__device__ double g_den;
__device__ unsigned g_bcount;

__device__ __forceinline__ float gval(int a, int b) {
    // sum_c |onehot(a)-onehot(b)|, onehot(IGNORE)=0
    if (a == b) return 0.0f;
    if (a == IGNORE || b == IGNORE) return 1.0f;
    return 2.0f;
}

__device__ __forceinline__ void stage_tile(const float* __restrict__ pred,
                                           int tile, float* __restrict__ sbuf,
                                           int tid) {
    const int base = tile * TV;
    #pragma unroll
    for (int r = 0; r < CHUNKS / 256; r++) {        // 5 chunks per thread
        const int k   = r * 256 + tid;
        const int c   = k >> 6;                     // chunk / 64  (64 chunks per channel)
        const int off = (k & 63) << 2;              // float offset within channel row
        const float* src = pred + c * SPATIAL + base + off;
        uint32_t dst = (uint32_t)__cvta_generic_to_shared(&sbuf[c * TV + off]);
        asm volatile("cp.async.cg.shared.global [%0], [%1], 16;\n" :: "r"(dst), "l"(src));
    }
}

__global__ void __launch_bounds__(256, 5)
loss_kernel(const float* __restrict__ pred,
            const int*   __restrict__ tgt,
            const float* __restrict__ cw,
            float* __restrict__ out) {
    __shared__ float s_pred[2][NUM_CLASS * TV];   // 2 x 20 KB
    __shared__ float s_num[8], s_den[8];

    const int tid = threadIdx.x;
    float num = 0.0f, den = 0.0f;

    // ---- prologue: prefetch first tile ----
    int tile = blockIdx.x;                         // GRID < NTILES always
    stage_tile(pred, tile, s_pred[0], tid);
    asm volatile("cp.async.commit_group;\n");

    int buf = 0;
    for (; tile < NTILES; tile += GRID, buf ^= 1) {
        // prefetch next tile into the other buffer (free since last iteration's sync)
        const int next = tile + GRID;
        if (next < NTILES) stage_tile(pred, next, s_pred[buf ^ 1], tid);
        asm volatile("cp.async.commit_group;\n");  // empty group OK on last iter

        asm volatile("cp.async.wait_group 1;\n");  // current tile's group complete
        __syncthreads();

        // ---- compute: 1 voxel per thread from SMEM ----
        const float* sb = s_pred[buf];
        const int s = tile * TV + tid;

        const int t = __ldg(&tgt[s]);
        const bool valid = (t != IGNORE);
        const int tc = valid ? t : 0;

        float sum = 0.0f;
        #pragma unroll
        for (int c = 0; c < NUM_CLASS; c++) {
            sum += __expf(sb[c * TV + tid]);       // MUFU.EX2, conflict-free LDS
        }
        const float vt = sb[tc * TV + tid];        // dynamic smem index, conflict-free
        const float logp_t = vt - __logf(sum);     // no max-sub: inputs ~N(0,1)

        const float w = __ldg(&cw[tc]);
        const float loss = valid ? (-w * logp_t) : 0.0f;
        den += valid ? w : 0.0f;

        // ---- LGA weight ----
        const int wq = s & (WW - 1);               // == lane id (warp spans one W row)
        const int h  = (s >> 5) & (HH - 1);
        const int d  = s >> 13;
        const int sd = WW * HH;

        float lga;
        {   // W axis: neighbors in adjacent lanes; shfl self-clamps at edges -> t
            int a = __shfl_up_sync(0xFFFFFFFFu, t, 1);
            int b = __shfl_down_sync(0xFFFFFFFFu, t, 1);
            float sc = (wq == 0 || wq == WW - 1) ? 1.0f : 0.5f;
            lga = sc * gval(a, b);
        }
        {   // H axis
            const int thm = (h == 0)      ? t : __ldg(&tgt[s - WW]);
            const int thp = (h == HH - 1) ? t : __ldg(&tgt[s + WW]);
            float sc = (h == 0 || h == HH - 1) ? 1.0f : 0.5f;
            lga += sc * gval(thm, thp);
        }
        {   // D axis
            const int tdm = (d == 0)      ? t : __ldg(&tgt[s - sd]);
            const int tdp = (d == DD - 1) ? t : __ldg(&tgt[s + sd]);
            float sc = (d == 0 || d == DD - 1) ? 1.0f : 0.5f;
            lga += sc * gval(tdm, tdp);
        }

        num += loss * (1.0f + lga);                // ALPHA=1, BETA=1

        __syncthreads();                           // buffer free for next prefetch
    }

    // ---- reduction: warp shuffle -> shared -> global double atomics ----
    #pragma unroll
    for (int off = 16; off > 0; off >>= 1) {
        num += __shfl_down_sync(0xFFFFFFFFu, num, off);
        den += __shfl_down_sync(0xFFFFFFFFu, den, off);
    }
    const int lane = tid & 31;
    const int wid  = tid >> 5;
    if (lane == 0) { s_num[wid] = num; s_den[wid] = den; }
    __syncthreads();

    if (tid == 0) {
        float bn = 0.f, bd = 0.f;
        #pragma unroll
        for (int i = 0; i < 8; i++) { bn += s_num[i]; bd += s_den[i]; }
        atomicAdd(&g_num, (double)bn);
        atomicAdd(&g_den, (double)bd);
        __threadfence();
        unsigned done = atomicAdd(&g_bcount, 1u);
        if (done == (unsigned)(gridDim.x - 1)) {
            double n  = atomicAdd(&g_num, 0.0);
            double dd = atomicAdd(&g_den, 0.0);
            out[0] = (float)(n / dd);
            g_num = 0.0; g_den = 0.0; g_bcount = 0u;
        }
    }
}

extern "C" void kernel_launch(void* const* d_in, const int* in_sizes, int n_in,
                              void* d_out, int out_size) {
    const float* pred = (const float*)d_in[0];
    const int*   tgt  = (const int*)d_in[1];
    const float* cw   = (const float*)d_in[2];
    float* out = (float*)d_out;

    loss_kernel<<<GRID, 256>>>(pred, tgt, cw, out);
}

// round 10
// speedup vs baseline: 1.1155x; 1.0298x over previous
#include <cuda_runtime.h>
#include <math.h>
#include <stdint.h>

#define NUM_CLASS 20
#define IGNORE 255
#define DD 256
#define HH 256
#define WW 32
#define SPATIAL (DD*HH*WW)     // 2,097,152
#define TV 256                 // voxels per tile (one block-wide pass)
#define NTILES (SPATIAL/TV)    // 8192
#define GRID 740               // 148 SMs x 5 persistent CTAs
#define CHUNKS (NUM_CLASS*TV*4/16)   // 1280 16-byte chunks per tile (5 per thread)

__device__ double g_num;        // zero at module load; reset by last block each run
__device__ double g_den;
__device__ unsigned g_bcount;

__device__ __forceinline__ float gval(int a, int b) {
    // sum_c |onehot(a)-onehot(b)|, onehot(IGNORE)=0
    if (a == b) return 0.0f;
    if (a == IGNORE || b == IGNORE) return 1.0f;
    return 2.0f;
}

__device__ __forceinline__ void stage_tile(const float* __restrict__ pred,
                                           int tile, float* __restrict__ sbuf,
                                           int tid) {
    const int base = tile * TV;
    #pragma unroll
    for (int r = 0; r < CHUNKS / 256; r++) {        // 5 chunks per thread
        const int k   = r * 256 + tid;
        const int c   = k >> 6;                     // 64 chunks per channel
        const int off = (k & 63) << 2;
        const float* src = pred + c * SPATIAL + base + off;
        uint32_t dst = (uint32_t)__cvta_generic_to_shared(&sbuf[c * TV + off]);
        asm volatile("cp.async.cg.shared.global [%0], [%1], 16;\n" :: "r"(dst), "l"(src));
    }
}

// Load the 5 target labels for voxel s with edge-clamped addresses
// (clamped address yields t itself, matching reference edge semantics).
__device__ __forceinline__ void load_targets(const int* __restrict__ tgt, int s,
                                             int& t, int& thm, int& thp,
                                             int& tdm, int& tdp) {
    const int h = (s >> 5) & (HH - 1);
    const int d = s >> 13;
    const int sd = WW * HH;
    t   = __ldg(&tgt[s]);
    thm = __ldg(&tgt[s - (h == 0      ? 0 : WW)]);
    thp = __ldg(&tgt[s + (h == HH - 1 ? 0 : WW)]);
    tdm = __ldg(&tgt[s - (d == 0      ? 0 : sd)]);
    tdp = __ldg(&tgt[s + (d == DD - 1 ? 0 : sd)]);
}

__global__ void __launch_bounds__(256, 5)
loss_kernel(const float* __restrict__ pred,
            const int*   __restrict__ tgt,
            const float* __restrict__ cw,
            float* __restrict__ out) {
    __shared__ float s_pred[2][NUM_CLASS * TV];   // 2 x 20 KB
    __shared__ float s_num[8], s_den[8];

    const int tid = threadIdx.x;
    float num = 0.0f, den = 0.0f;

    // ---- prologue: prefetch first tile (data + targets) ----
    int tile = blockIdx.x;                         // GRID < NTILES always
    stage_tile(pred, tile, s_pred[0], tid);
    asm volatile("cp.async.commit_group;\n");
    int tC, thmC, thpC, tdmC, tdpC;
    load_targets(tgt, tile * TV + tid, tC, thmC, thpC, tdmC, tdpC);

    int buf = 0;
    for (; tile < NTILES; tile += GRID, buf ^= 1) {
        // prefetch next tile: predictions into other buffer + targets into regs
        const int next = tile + GRID;
        int tN, thmN, thpN, tdmN, tdpN;
        if (next < NTILES) {
            stage_tile(pred, next, s_pred[buf ^ 1], tid);
            load_targets(tgt, next * TV + tid, tN, thmN, thpN, tdmN, tdpN);
        } else {
            tN = thmN = thpN = tdmN = tdpN = 0;
        }
        asm volatile("cp.async.commit_group;\n");  // empty group OK on last iter

        asm volatile("cp.async.wait_group 1;\n");  // current tile's group complete
        __syncthreads();

        // ---- compute current tile: 1 voxel/thread from SMEM, targets already in regs ----
        const float* sb = s_pred[buf];
        const int s = tile * TV + tid;
        const int t = tC;

        const bool valid = (t != IGNORE);
        const int tc = valid ? t : 0;

        float sum = 0.0f;
        #pragma unroll
        for (int c = 0; c < NUM_CLASS; c++) {
            sum += __expf(sb[c * TV + tid]);       // MUFU.EX2, conflict-free LDS
        }
        const float vt = sb[tc * TV + tid];        // dynamic smem index, conflict-free
        const float logp_t = vt - __logf(sum);     // no max-sub: inputs ~N(0,1)

        const float w = __ldg(&cw[tc]);            // 80B table: L1-resident
        const float loss = valid ? (-w * logp_t) : 0.0f;
        den += valid ? w : 0.0f;

        // ---- LGA weight ----
        const int wq = s & (WW - 1);               // == lane id (warp spans one W row)
        const int h  = (s >> 5) & (HH - 1);
        const int d  = s >> 13;

        float lga;
        {   // W axis: neighbors in adjacent lanes; shfl self-clamps at edges -> t
            int a = __shfl_up_sync(0xFFFFFFFFu, t, 1);
            int b = __shfl_down_sync(0xFFFFFFFFu, t, 1);
            float sc = (wq == 0 || wq == WW - 1) ? 1.0f : 0.5f;
            lga = sc * gval(a, b);
        }
        {   // H axis (edge handled by clamped-address load -> thm/thp == t)
            float sc = (h == 0 || h == HH - 1) ? 1.0f : 0.5f;
            lga += sc * gval(thmC, thpC);
        }
        {   // D axis
            float sc = (d == 0 || d == DD - 1) ? 1.0f : 0.5f;
            lga += sc * gval(tdmC, tdpC);
        }

        num += loss * (1.0f + lga);                // ALPHA=1, BETA=1

        __syncthreads();                           // buffer free for next prefetch

        // rotate target registers
        tC = tN; thmC = thmN; thpC = thpN; tdmC = tdmN; tdpC = tdpN;
    }

    // ---- reduction: warp shuffle -> shared -> global double atomics ----
    #pragma unroll
    for (int off = 16; off > 0; off >>= 1) {
        num += __shfl_down_sync(0xFFFFFFFFu, num, off);
        den += __shfl_down_sync(0xFFFFFFFFu, den, off);
    }
    const int lane = tid & 31;
    const int wid  = tid >> 5;
    if (lane == 0) { s_num[wid] = num; s_den[wid] = den; }
    __syncthreads();

    if (tid == 0) {
        float bn = 0.f, bd = 0.f;
        #pragma unroll
        for (int i = 0; i < 8; i++) { bn += s_num[i]; bd += s_den[i]; }
        atomicAdd(&g_num, (double)bn);
        atomicAdd(&g_den, (double)bd);
        __threadfence();
        unsigned done = atomicAdd(&g_bcount, 1u);
        if (done == (unsigned)(gridDim.x - 1)) {
            double n  = atomicAdd(&g_num, 0.0);
            double dd = atomicAdd(&g_den, 0.0);
            out[0] = (float)(n / dd);
            g_num = 0.0; g_den = 0.0; g_bcount = 0u;
        }
    }
}

extern "C" void kernel_launch(void* const* d_in, const int* in_sizes, int n_in,
                              void* d_out, int out_size) {
    const float* pred = (const float*)d_in[0];
    const int*   tgt  = (const int*)d_in[1];
    const float* cw   = (const float*)d_in[2];
    float* out = (float*)d_out;

    loss_kernel<<<GRID, 256>>>(pred, tgt, cw, out);
}